// round 14
// baseline (speedup 1.0000x reference)
#include <cuda_runtime.h>

// ZapBench volume sampler: quadrilinear (trilinear spatial + linear temporal)
// frames: (T=3, Z=72, Y=512, X=1024) fp32, coords: (N, 4) fp32 [z, y, x, t]
// out: (N, 1) fp32
//
// R12-14: single-pass padded-bin sort (1728 bins x 4096 slots, t innermost;
// one fused kernel bins + reserves + places; overflow -> side list), then a
// tiled gather kernel with float4-window loads. R14: overflow handling folded
// into the tiles kernel (one less launch), __stcs output stores, sort unroll.

#define T_DIM 3
#define Z_DIM 72
#define Y_DIM 512
#define X_DIM 1024

#define NBINS (9 * 8 * 8 * 3)    // (z/8, y/64, x/128) spatial, t0 innermost
#define BIN_CAP 4096             // slots per bin (mean fill ~2427)
#define TILES (BIN_CAP / 256)    // 16 sample tiles per bin
#define OVF_BLOCKS 64
#define CAP   (1 << 22)          // 4194304 points
#define CHUNK 4096               // points per fused-sort CTA
#define SORT_THREADS 512

__device__ unsigned int g_fill[NBINS];
__device__ unsigned int g_sorted_idx[NBINS * BIN_CAP];   // 28.3 MB
__device__ unsigned int g_ovf_cnt;
__device__ unsigned int g_ovf[CAP];                      // worst-case safe

__device__ __forceinline__ int compute_bin(float4 c)
{
    float t_abs = c.w * 3.0f;
    int t0 = min(max((int)t_abs, 0), 2);
    int zc = min(max((int)(c.x * (float)(Z_DIM - 1)), 0), Z_DIM - 1) >> 3;   // 0..8
    int yc = min(max((int)(c.y * (float)(Y_DIM - 1)), 0), Y_DIM - 1) >> 6;   // 0..7
    int xc = min(max((int)(c.z * (float)(X_DIM - 1)), 0), X_DIM - 1) >> 7;   // 0..7
    return (((zc * 8 + yc) * 8 + xc) * 3) + t0;   // t innermost
}

__global__ void zero_kernel()
{
    int i = blockIdx.x * blockDim.x + threadIdx.x;
    if (i < NBINS) g_fill[i] = 0;
    if (i == 0) g_ovf_cnt = 0;
}

// Fused sort: bin ids stay in smem; one global atomicAdd per (CTA, bin).
__global__ void __launch_bounds__(SORT_THREADS)
fused_sort_kernel(const float4* __restrict__ coords, int n)
{
    __shared__ unsigned short s_bin[CHUNK];
    __shared__ unsigned int   s_hist[NBINS];
    __shared__ unsigned int   s_base[NBINS];

    int start = blockIdx.x * CHUNK;
    int m = min(n - start, CHUNK);
    if (m <= 0) return;

    for (int b = threadIdx.x; b < NBINS; b += SORT_THREADS) s_hist[b] = 0;
    __syncthreads();

    #pragma unroll 4
    for (int k = threadIdx.x; k < m; k += SORT_THREADS) {
        float4 c = __ldg(&coords[start + k]);
        int bin = compute_bin(c);
        s_bin[k] = (unsigned short)bin;
        atomicAdd(&s_hist[bin], 1u);
    }
    __syncthreads();

    for (int b = threadIdx.x; b < NBINS; b += SORT_THREADS) {
        unsigned int cnt = s_hist[b];
        s_base[b] = cnt ? atomicAdd(&g_fill[b], cnt) : 0u;
        s_hist[b] = 0;
    }
    __syncthreads();

    #pragma unroll 8
    for (int k = threadIdx.x; k < m; k += SORT_THREADS) {
        int bin = s_bin[k];
        unsigned int off = s_base[bin] + atomicAdd(&s_hist[bin], 1u);
        unsigned int idx = (unsigned int)(start + k);
        if (off < BIN_CAP) {
            g_sorted_idx[(unsigned int)bin * BIN_CAP + off] = idx;
        } else {
            unsigned int p = atomicAdd(&g_ovf_cnt, 1u);
            g_ovf[p] = idx;   // p < CAP always (total points <= CAP)
        }
    }
}

__device__ __forceinline__ float f4_sel(float4 q, int k)
{
    float lo = (k & 1) ? q.y : q.x;
    float hi = (k & 1) ? q.w : q.z;
    return (k & 2) ? hi : lo;
}

// Sample both x-texels of one row using an aligned float4 window.
__device__ __forceinline__ float row_lerp(
    const float4* __restrict__ row, int b4, int off, int a4, int ao, float wx)
{
    float4 q = __ldg(row + b4);
    float4 q2 = q;
    if (a4 != b4) q2 = __ldg(row + a4);
    float c0 = f4_sel(q, off);
    float c1 = f4_sel(q2, ao);
    return fmaf(wx, c1 - c0, c0);
}

__device__ __forceinline__ float trilerp_slice4(
    const float* __restrict__ f, int t,
    int z0, int z1, int y0, int y1,
    int b4, int off, int a4, int ao,
    float wz, float wy, float wx)
{
    const int tb = t * Z_DIM;
    const float4* r00 = (const float4*)f + ((long)((tb + z0) * Y_DIM + y0) << 8);
    const float4* r01 = (const float4*)f + ((long)((tb + z0) * Y_DIM + y1) << 8);
    const float4* r10 = (const float4*)f + ((long)((tb + z1) * Y_DIM + y0) << 8);
    const float4* r11 = (const float4*)f + ((long)((tb + z1) * Y_DIM + y1) << 8);

    float c00 = row_lerp(r00, b4, off, a4, ao, wx);
    float c01 = row_lerp(r01, b4, off, a4, ao, wx);
    float c10 = row_lerp(r10, b4, off, a4, ao, wx);
    float c11 = row_lerp(r11, b4, off, a4, ao, wx);

    float c0 = fmaf(wy, c01 - c00, c00);
    float c1 = fmaf(wy, c11 - c10, c10);
    return fmaf(wz, c1 - c0, c0);
}

__device__ __forceinline__ float sample_point(
    const float4 c, const float* __restrict__ frames)
{
    float t_abs = c.w * 3.0f;
    int t0 = min(max((int)t_abs, 0), 2);
    int t1 = min(t0 + 1, T_DIM - 1);
    float w = t_abs - (float)t0;

    float sz = c.x * (float)(Z_DIM - 1);
    float sy = c.y * (float)(Y_DIM - 1);
    float sx = c.z * (float)(X_DIM - 1);

    int iz = (int)sz;   // inputs in [0,1): trunc == floor
    int iy = (int)sy;
    int ix = (int)sx;

    float wz = sz - (float)iz;
    float wy = sy - (float)iy;
    float wx = sx - (float)ix;

    int z0 = max(0, min(iz, Z_DIM - 1));
    int y0 = max(0, min(iy, Y_DIM - 1));
    int x0 = max(0, min(ix, X_DIM - 1));
    int z1 = min(z0 + 1, Z_DIM - 1);
    int y1 = min(y0 + 1, Y_DIM - 1);
    int x1 = min(x0 + 1, X_DIM - 1);

    int b4 = x0 >> 2, off = x0 & 3;
    int a4 = x1 >> 2, ao  = x1 & 3;

    float val0 = trilerp_slice4(frames, t0, z0, z1, y0, y1, b4, off, a4, ao, wz, wy, wx);

    if (t1 != t0) {
        float val1 = trilerp_slice4(frames, t1, z0, z1, y0, y1, b4, off, a4, ao, wz, wy, wx);
        return fmaf(w, val1 - val0, val0);
    }
    return val0;
}

// One CTA per (bin, tile); trailing OVF_BLOCKS CTAs drain the overflow list.
__global__ void __launch_bounds__(256)
sample_tiles_kernel(const float4* __restrict__ coords,
                    const float*  __restrict__ frames,
                    float*        __restrict__ out)
{
    int blk = blockIdx.x;

    if (blk >= NBINS * TILES) {
        // Overflow path (rare; usually g_ovf_cnt == 0).
        int ob = blk - NBINS * TILES;
        unsigned int cnt = g_ovf_cnt;
        if (cnt > (unsigned int)CAP) cnt = CAP;
        unsigned int stride = OVF_BLOCKS * 256;
        for (unsigned int k = ob * 256 + threadIdx.x; k < cnt; k += stride) {
            unsigned int i = g_ovf[k];
            float4 c = __ldg(&coords[i]);
            __stcs(&out[i], sample_point(c, frames));
        }
        return;
    }

    int bin  = blk / TILES;
    int tile = blk % TILES;

    unsigned int cnt = __ldg(&g_fill[bin]);
    if (cnt > BIN_CAP) cnt = BIN_CAP;

    unsigned int j = tile * 256 + threadIdx.x;
    if (j >= cnt) return;

    unsigned int i = __ldg(&g_sorted_idx[(unsigned int)bin * BIN_CAP + j]);
    float4 c = __ldg(&coords[i]);
    __stcs(&out[i], sample_point(c, frames));
}

__global__ void __launch_bounds__(256)
sample_direct_kernel(const float4* __restrict__ coords,
                     const float*  __restrict__ frames,
                     float*        __restrict__ out,
                     int n)
{
    int i = blockIdx.x * blockDim.x + threadIdx.x;
    if (i >= n) return;
    float4 c = __ldg(&coords[i]);
    out[i] = sample_point(c, frames);
}

extern "C" void kernel_launch(void* const* d_in, const int* in_sizes, int n_in,
                              void* d_out, int out_size)
{
    const float4* coords = (const float4*)d_in[0];
    const float*  frames = (const float*)d_in[1];
    float* out = (float*)d_out;

    int n = in_sizes[0] / 4;   // coords is (N,4) floats

    if (n > CAP) {
        int blocks = (n + 255) / 256;
        sample_direct_kernel<<<blocks, 256>>>(coords, frames, out, n);
        return;
    }

    int sort_blocks = (n + CHUNK - 1) / CHUNK;

    zero_kernel<<<(NBINS + 255) / 256, 256>>>();
    fused_sort_kernel<<<sort_blocks, SORT_THREADS>>>(coords, n);
    sample_tiles_kernel<<<NBINS * TILES + OVF_BLOCKS, 256>>>(coords, frames, out);
}